// round 2
// baseline (speedup 1.0000x reference)
#include <cuda_runtime.h>

// out[j] = x[j - offset] for 0 <= j-offset < n, else 0.
// offset = trunc(w_row + row_length * w_col), read from device scalars.
//
// Fully-aligned formulation: offset = 4*m + r (floor decomposition).
// Output vector g needs words from source vectors (g-m-1) and (g-m).
// Each thread loads the aligned vector v = x4[g-m]; the previous vector p
// arrives via warp shuffle (lane 0 loads it directly). Since n % 4 == 0,
// predicating whole vectors to zero when out of range reproduces the
// boundary zero-fill exactly.

__global__ void __launch_bounds__(256)
shift_realign(const float4* __restrict__ x4,
              const float* __restrict__ w_row,
              const float* __restrict__ w_col,
              int row_length, int n,
              float4* __restrict__ out4)
{
    const int nv = n >> 2;
    const int offset = (int)(w_row[0] + (float)row_length * w_col[0]);
    const int r = offset & 3;            // 0..3, also correct for negative offset
    const int m = (offset - r) >> 2;     // floor(offset/4)

    const int g = blockIdx.x * blockDim.x + threadIdx.x;
    const bool active = (g < nv);
    const int sv = g - m;                // source vector holding the high words

    float4 v = make_float4(0.f, 0.f, 0.f, 0.f);
    if (active && sv >= 0 && sv < nv)
        v = __ldcs(x4 + sv);

    // p = previous thread's v (source vector sv-1)
    float4 p;
    p.x = __shfl_up_sync(0xffffffffu, v.x, 1);
    p.y = __shfl_up_sync(0xffffffffu, v.y, 1);
    p.z = __shfl_up_sync(0xffffffffu, v.z, 1);
    p.w = __shfl_up_sync(0xffffffffu, v.w, 1);

    if (r != 0 && (threadIdx.x & 31) == 0) {
        // lane 0's shfl_up is undefined-self; fetch sv-1 directly (L2-hot line)
        const int pv = sv - 1;
        if (active && pv >= 0 && pv < nv)
            p = __ldcs(x4 + pv);
        else
            p = make_float4(0.f, 0.f, 0.f, 0.f);
    }

    float4 o;
    if (r == 0)      o = v;
    else if (r == 1) o = make_float4(p.w, v.x, v.y, v.z);
    else if (r == 2) o = make_float4(p.z, p.w, v.x, v.y);
    else             o = make_float4(p.y, p.z, p.w, v.x);

    if (active)
        __stcs(out4 + g, o);
}

extern "C" void kernel_launch(void* const* d_in, const int* in_sizes, int n_in,
                              void* d_out, int out_size)
{
    const float* x     = (const float*)d_in[0];
    const float* w_row = (const float*)d_in[1];
    const float* w_col = (const float*)d_in[2];

    const int n = in_sizes[0];
    // n = row_length^2 (8192^2 here); derive row_length on host.
    int row_length = 1;
    while ((long long)row_length * row_length < (long long)n) row_length <<= 1;

    const int nv = n >> 2;
    const int threads = 256;
    const int blocks = (nv + threads - 1) / threads;

    shift_realign<<<blocks, threads>>>((const float4*)x, w_row, w_col,
                                       row_length, n, (float4*)d_out);
}

// round 3
// speedup vs baseline: 1.0742x; 1.0742x over previous
#include <cuda_runtime.h>

#define FULL_MASK 0xffffffffu

// out[j] = x[j - offset] for 0 <= j-offset < n else 0, offset from device scalars.
// Warp tile: 128 consecutive output vectors per warp; thread handles k=0..3 at
// lane-contiguous addresses (full coalescing, MLP=4 front-batched aligned loads).
// Misalignment r = offset & 3 fixed via minimal warp shuffles of the needed
// prev-vector words. n % 4 == 0 so whole-vector zero predication is exact.

__global__ void __launch_bounds__(256)
shift_warptile(const float4* __restrict__ x4,
               const float*  __restrict__ xs,
               const float*  __restrict__ w_row,
               const float*  __restrict__ w_col,
               int row_length, int n,
               float4* __restrict__ out4)
{
    const int nv = n >> 2;
    const int offset = (int)(w_row[0] + (float)row_length * w_col[0]);
    const int r = offset & 3;
    const int m = (offset - r) >> 2;          // floor(offset/4)

    const int warp_id = (blockIdx.x * blockDim.x + threadIdx.x) >> 5;
    const int lane    = threadIdx.x & 31;
    const int wbase   = warp_id << 7;         // 128 vectors per warp

    // Front-batched independent aligned loads (MLP = 4).
    float4 v[4];
    int g0 = wbase + lane;
#pragma unroll
    for (int k = 0; k < 4; k++) {
        const int g  = g0 + (k << 5);
        const int sv = g - m;
        float4 t = make_float4(0.f, 0.f, 0.f, 0.f);
        if (g < nv && sv >= 0 && sv < nv) t = __ldcs(x4 + sv);
        v[k] = t;
    }

    if (r == 0) {
#pragma unroll
        for (int k = 0; k < 4; k++) {
            const int g = g0 + (k << 5);
            if (g < nv) __stcs(out4 + g, v[k]);
        }
        return;
    }

    // Extra boundary words for lane 0, k = 0: words (4-r..3) of vector wbase-m-1.
    // Element index of word c: 4*(wbase - m) - 4 + c.
    float e_y = 0.f, e_z = 0.f, e_w = 0.f;
    if (lane == 0) {
        const int ebase = 4 * (wbase - m) - 4;
        if (r >= 3) { int i = ebase + 1; if (i >= 0 && i < n) e_y = __ldcs(xs + i); }
        if (r >= 2) { int i = ebase + 2; if (i >= 0 && i < n) e_z = __ldcs(xs + i); }
        /* r>=1 */ { int i = ebase + 3; if (i >= 0 && i < n) e_w = __ldcs(xs + i); }
    }

    // prev-word fetch: value of component from vector (g-m-1) =
    //   lane>0 : lane-1's v[k];  lane0,k>0 : lane31's v[k-1];  lane0,k0 : e_*
#define PREVW(comp, k, evar, dst)                                              \
    do {                                                                       \
        float _up  = __shfl_up_sync(FULL_MASK, v[k].comp, 1);                  \
        float _b31 = __shfl_sync(FULL_MASK, (k) > 0 ? v[(k)>0?(k)-1:0].comp    \
                                                    : 0.f, 31);                \
        dst = (lane == 0) ? ((k) > 0 ? _b31 : (evar)) : _up;                   \
    } while (0)

#pragma unroll
    for (int k = 0; k < 4; k++) {
        float pw, pz, py;
        PREVW(w, k, e_w, pw);
        float4 o;
        if (r == 1) {
            o = make_float4(pw, v[k].x, v[k].y, v[k].z);
        } else if (r == 2) {
            PREVW(z, k, e_z, pz);
            o = make_float4(pz, pw, v[k].x, v[k].y);
        } else {
            PREVW(z, k, e_z, pz);
            PREVW(y, k, e_y, py);
            o = make_float4(py, pz, pw, v[k].x);
        }
        const int g = g0 + (k << 5);
        if (g < nv) __stcs(out4 + g, o);
    }
#undef PREVW
}

extern "C" void kernel_launch(void* const* d_in, const int* in_sizes, int n_in,
                              void* d_out, int out_size)
{
    const float* x     = (const float*)d_in[0];
    const float* w_row = (const float*)d_in[1];
    const float* w_col = (const float*)d_in[2];

    const int n = in_sizes[0];
    int row_length = 1;
    while ((long long)row_length * row_length < (long long)n) row_length <<= 1;

    const int nv = n >> 2;                    // output float4 count
    const int warps = (nv + 127) >> 7;        // 128 vectors per warp
    const int threads = 256;
    const int blocks = (warps * 32 + threads - 1) / threads;

    shift_warptile<<<blocks, threads>>>((const float4*)x, x, w_row, w_col,
                                        row_length, n, (float4*)d_out);
}